// round 3
// baseline (speedup 1.0000x reference)
#include <cuda_runtime.h>
#include <math.h>

// Shapes (fixed for this problem)
//   x: [32, 256, 64, 64]; all 3x3 convs Cin=256; H=W=64
#define CIN   256
#define HH    64
#define WW    64
#define NPIX  4096
#define BATCH 32
#define KPTS  17

// Output layout (flattened tuple, fp32):
//   heat   [32,17,64,64]   @ 0          (2,228,224)
//   off    [32,34,64,64]   @ 2,228,224  (4,456,448)
//   var    [32,17,64,64]   @ 6,684,672  (2,228,224)
//   fw     scalar          @ 8,912,896
//   coords [32,17,2]       @ 8,912,897  (1,088)
//   scores [32,17]         @ 8,913,985  (544)

// Scratch (device globals — no runtime allocation allowed)
__device__ float g_buf0[33554432];   // 128 MiB
__device__ float g_buf1[33554432];   // 128 MiB

// ---------------------------------------------------------------------------
// 3x3 SAME conv + fused BN(scale=g/sqrt(1+eps)) + ReLU.
// Block: 64 couts x (8 rows x 32 cols) pixels. 256 threads.
// Per-thread micro-tile: 8 couts x 8 rows (one column = lane).
// ---------------------------------------------------------------------------
__global__ __launch_bounds__(256) void conv3x3_bn(
    const float* __restrict__ in, const float* __restrict__ w,
    const float* __restrict__ gma, const float* __restrict__ bta,
    float* __restrict__ out, int Cout)
{
    constexpr int CI_T = 8;
    __shared__ float s_in[CI_T * 10 * 34];     // [ci][r(10)][c(34)]
    __shared__ float s_w [64 * CI_T * 9];      // [co][ci*9+k]

    const int tid  = threadIdx.x;
    const int lane = tid & 31;
    const int wrp  = tid >> 5;
    const int n    = blockIdx.y;
    const int col0 = (blockIdx.x & 1) * 32;
    const int row0 = (blockIdx.x >> 1) * 8;
    const int co0  = blockIdx.z * 64;

    float acc[8][8];
#pragma unroll
    for (int i = 0; i < 8; i++)
#pragma unroll
        for (int r = 0; r < 8; r++) acc[i][r] = 0.f;

    for (int cb = 0; cb < CIN; cb += CI_T) {
        // ---- stage input halo tile (CI_T x 10 x 34) ----
        const float* inb = in + (n * CIN + cb) * NPIX;
        for (int idx = tid; idx < CI_T * 340; idx += 256) {
            const int c  = idx % 34;
            const int t  = idx / 34;
            const int r  = t % 10;
            const int ci = t / 10;
            const int gy = row0 + r - 1;
            const int gx = col0 + c - 1;
            float v = 0.f;
            if (gy >= 0 && gy < HH && gx >= 0 && gx < WW)
                v = inb[ci * NPIX + gy * WW + gx];
            s_in[idx] = v;   // idx == ci*340 + r*34 + c
        }
        // ---- stage weights (64 co x 72 contiguous (ci,k)) ----
        const float* wb = w + co0 * (CIN * 9) + cb * 9;
        for (int idx = tid; idx < 64 * 72; idx += 256) {
            const int kk = idx % 72;
            const int co = idx / 72;
            s_w[idx] = wb[co * (CIN * 9) + kk];
        }
        __syncthreads();

        // ---- compute ----
#pragma unroll 1
        for (int ci = 0; ci < CI_T; ci++) {
#pragma unroll
            for (int ky = 0; ky < 3; ky++) {
#pragma unroll
                for (int kx = 0; kx < 3; kx++) {
                    float iv[8];
#pragma unroll
                    for (int r = 0; r < 8; r++)
                        iv[r] = s_in[ci * 340 + (r + ky) * 34 + lane + kx];
                    const int kk = ci * 9 + ky * 3 + kx;
#pragma unroll
                    for (int i = 0; i < 8; i++) {
                        const float wv = s_w[(wrp * 8 + i) * 72 + kk];  // warp-uniform
#pragma unroll
                        for (int r = 0; r < 8; r++)
                            acc[i][r] = fmaf(wv, iv[r], acc[i][r]);
                    }
                }
            }
        }
        __syncthreads();
    }

    // ---- epilogue: BN + ReLU, coalesced stores ----
    const float is = rsqrtf(1.0f + 1e-5f);
#pragma unroll
    for (int i = 0; i < 8; i++) {
        const int co = co0 + wrp * 8 + i;
        const float sc = gma[co] * is;
        const float bs = bta[co];
#pragma unroll
        for (int r = 0; r < 8; r++) {
            const float v = fmaxf(acc[i][r] * sc + bs, 0.f);
            out[((n * Cout + co) * HH + row0 + r) * WW + col0 + lane] = v;
        }
    }
}

// ---------------------------------------------------------------------------
// 1x1 conv head: out[n,co,p] = sum_ci in[n,ci,p]*w[co,ci] + bias[co]
// Optional softplus. One thread per pixel, acc[CO] in registers.
// ---------------------------------------------------------------------------
template <int CI, int CO, bool SOFTPLUS>
__global__ __launch_bounds__(256) void conv1x1_k(
    const float* __restrict__ in, const float* __restrict__ w,
    const float* __restrict__ bias, float* __restrict__ out)
{
    __shared__ float s_w[CI * CO];   // [ci][co]
    const int tid = threadIdx.x;
    for (int i = tid; i < CI * CO; i += 256) {
        const int co = i / CI;
        const int ci = i % CI;
        s_w[ci * CO + co] = w[i];
    }
    __syncthreads();

    const int pid = blockIdx.x * 256 + tid;
    const int n = pid >> 12;
    const int p = pid & 4095;
    const float* ip = in + n * CI * NPIX + p;

    float acc[CO];
#pragma unroll
    for (int c = 0; c < CO; c++) acc[c] = 0.f;

#pragma unroll 4
    for (int ci = 0; ci < CI; ci++) {
        const float v = ip[ci * NPIX];
#pragma unroll
        for (int co = 0; co < CO; co++)
            acc[co] = fmaf(v, s_w[ci * CO + co], acc[co]);
    }

#pragma unroll
    for (int co = 0; co < CO; co++) {
        float v = acc[co] + bias[co];
        if (SOFTPLUS)
            v = (v > 0.f) ? (v + log1pf(expf(-v))) : log1pf(expf(v));
        out[(n * CO + co) * NPIX + p] = v;
    }
}

// ---------------------------------------------------------------------------
// Fused postprocessing: per (b,k) block.
//   soft_argmax (full 64x64 softmax) + max score
//   local_refine (5x5 masked softmax around rounded peak)
//   coords = sigmoid(alpha)*cg + (1-a)*cl, then += sigmoid(fusion)*bilinear(off)
// ---------------------------------------------------------------------------
__global__ __launch_bounds__(256) void postproc_k(
    const float* __restrict__ heat, const float* __restrict__ off,
    const float* __restrict__ alpha_p, const float* __restrict__ fusion_p,
    float* __restrict__ fw_out, float* __restrict__ coords_out,
    float* __restrict__ scores_out)
{
    __shared__ float r0[256], r1[256], r2[256];
    const int bk  = blockIdx.x;          // b*17 + k
    const int tid = threadIdx.x;
    const float* hm = heat + (size_t)bk * NPIX;

    // --- block max ---
    float lm = -1e30f;
#pragma unroll
    for (int i = 0; i < 16; i++) lm = fmaxf(lm, hm[tid + i * 256]);
    r0[tid] = lm;
    __syncthreads();
    for (int s = 128; s > 0; s >>= 1) {
        if (tid < s) r0[tid] = fmaxf(r0[tid], r0[tid + s]);
        __syncthreads();
    }
    const float m = r0[0];
    __syncthreads();

    // --- softmax moments ---
    float se = 0.f, sx = 0.f, sy = 0.f;
#pragma unroll
    for (int i = 0; i < 16; i++) {
        const int idx = tid + i * 256;
        const float e = expf(hm[idx] - m);
        se += e;
        sx += e * (float)(idx & 63);
        sy += e * (float)(idx >> 6);
    }
    r0[tid] = se; r1[tid] = sx; r2[tid] = sy;
    __syncthreads();
    for (int s = 128; s > 0; s >>= 1) {
        if (tid < s) {
            r0[tid] += r0[tid + s];
            r1[tid] += r1[tid + s];
            r2[tid] += r2[tid + s];
        }
        __syncthreads();
    }

    if (tid == 0) {
        const float inv = 1.f / r0[0];
        const float xc = r1[0] * inv;
        const float yc = r2[0] * inv;

        // local_refine: 5x5 masked softmax (rintf = round-half-even == jnp.round)
        const int px = (int)rintf(fminf(fmaxf(xc, 0.f), 63.f));
        const int py = (int)rintf(fminf(fmaxf(yc, 0.f), 63.f));
        int pxs[5], pys[5]; bool okx[5], oky[5];
#pragma unroll
        for (int i = 0; i < 5; i++) {
            const int xs = px - 2 + i; okx[i] = (xs >= 0 && xs < WW); pxs[i] = min(max(xs, 0), 63);
            const int ys = py - 2 + i; oky[i] = (ys >= 0 && ys < HH); pys[i] = min(max(ys, 0), 63);
        }
        float pv[25];
        float pm = -1e30f;
        for (int j = 0; j < 5; j++)
            for (int i = 0; i < 5; i++) {
                const float v = hm[pys[j] * WW + pxs[i]];
                pv[j * 5 + i] = v;
                if (okx[i] && oky[j]) pm = fmaxf(pm, v);
            }
        float ws = 0.f, rx = 0.f, ry = 0.f;
        for (int j = 0; j < 5; j++)
            for (int i = 0; i < 5; i++)
                if (okx[i] && oky[j]) {
                    const float e = expf(pv[j * 5 + i] - pm);
                    ws += e;
                    rx += e * (float)pxs[i];
                    ry += e * (float)pys[j];
                }
        rx /= ws; ry /= ws;

        const float a   = 1.f / (1.f + expf(-alpha_p[0]));
        const float fwv = 1.f / (1.f + expf(-fusion_p[0]));
        float cx = a * xc + (1.f - a) * rx;
        float cy = a * yc + (1.f - a) * ry;

        // bilinear sample of off at (cx, cy)
        const float ix = fminf(fmaxf(cx, 0.f), 63.f);
        const float iy = fminf(fmaxf(cy, 0.f), 63.f);
        const float x0f = floorf(ix), y0f = floorf(iy);
        const float wx = ix - x0f, wy = iy - y0f;
        const int x0 = min(max((int)x0f, 0), 63);
        const int y0 = min(max((int)y0f, 0), 63);
        const int x1 = min(x0 + 1, 63);
        const int y1 = min(y0 + 1, 63);
        // off channel (k*2+ch) of batch b: offset = bk*2*NPIX + ch*NPIX
        const float* ob = off + (size_t)bk * 2 * NPIX;
        float sv[2];
#pragma unroll
        for (int ch = 0; ch < 2; ch++) {
            const float* o = ob + ch * NPIX;
            const float v00 = o[y0 * WW + x0], v01 = o[y0 * WW + x1];
            const float v10 = o[y1 * WW + x0], v11 = o[y1 * WW + x1];
            sv[ch] = (1.f - wy) * ((1.f - wx) * v00 + wx * v01)
                   + wy * ((1.f - wx) * v10 + wx * v11);
        }
        cx += fwv * sv[0];
        cy += fwv * sv[1];

        coords_out[bk * 2 + 0] = cx;
        coords_out[bk * 2 + 1] = cy;
        scores_out[bk] = m;
        if (bk == 0) fw_out[0] = fwv;
    }
}

// ---------------------------------------------------------------------------
extern "C" void kernel_launch(void* const* d_in, const int* in_sizes, int n_in,
                              void* d_out, int out_size)
{
    const float* x    = (const float*)d_in[0];
    const float* w_s1 = (const float*)d_in[1];
    const float* g_s1 = (const float*)d_in[2];
    const float* b_s1 = (const float*)d_in[3];
    const float* w_s2 = (const float*)d_in[4];
    const float* g_s2 = (const float*)d_in[5];
    const float* b_s2 = (const float*)d_in[6];
    const float* w_h1 = (const float*)d_in[7];
    const float* g_h1 = (const float*)d_in[8];
    const float* b_h1 = (const float*)d_in[9];
    const float* w_h2 = (const float*)d_in[10];
    const float* c_h2 = (const float*)d_in[11];
    const float* w_o1 = (const float*)d_in[12];
    const float* g_o1 = (const float*)d_in[13];
    const float* b_o1 = (const float*)d_in[14];
    const float* w_o2 = (const float*)d_in[15];
    const float* c_o2 = (const float*)d_in[16];
    const float* w_v1 = (const float*)d_in[17];
    const float* g_v1 = (const float*)d_in[18];
    const float* b_v1 = (const float*)d_in[19];
    const float* w_v2 = (const float*)d_in[20];
    const float* c_v2 = (const float*)d_in[21];
    const float* alpha  = (const float*)d_in[22];
    const float* fusion = (const float*)d_in[23];

    float* out    = (float*)d_out;
    float* heat   = out;                 // 2,228,224
    float* offp   = out + 2228224;       // 4,456,448
    float* varp   = out + 6684672;       // 2,228,224
    float* fwp    = out + 8912896;       // 1
    float* coords = out + 8912897;       // 1,088
    float* scores = out + 8913985;       // 544

    float *b0, *b1;
    cudaGetSymbolAddress((void**)&b0, g_buf0);
    cudaGetSymbolAddress((void**)&b1, g_buf1);

    dim3 blk(256);
    dim3 g256(16, BATCH, 4);   // Cout=256
    dim3 g128(16, BATCH, 2);   // Cout=128

    // stem
    conv3x3_bn<<<g256, blk>>>(x,  w_s1, g_s1, b_s1, b0, 256);
    conv3x3_bn<<<g256, blk>>>(b0, w_s2, g_s2, b_s2, b1, 256);   // b1 = s

    // heatmap head
    conv3x3_bn<<<g256, blk>>>(b1, w_h1, g_h1, b_h1, b0, 256);
    conv1x1_k<256, 17, false><<<512, blk>>>(b0, w_h2, c_h2, heat);

    // offset head
    conv3x3_bn<<<g256, blk>>>(b1, w_o1, g_o1, b_o1, b0, 256);
    conv1x1_k<256, 34, false><<<512, blk>>>(b0, w_o2, c_o2, offp);

    // variance head (softplus)
    conv3x3_bn<<<g128, blk>>>(b1, w_v1, g_v1, b_v1, b0, 128);
    conv1x1_k<128, 17, true><<<512, blk>>>(b0, w_v2, c_v2, varp);

    // fused soft-argmax + refine + offset sampling
    postproc_k<<<BATCH * KPTS, blk>>>(heat, offp, alpha, fusion,
                                      fwp, coords, scores);
}

// round 5
// speedup vs baseline: 4.7645x; 4.7645x over previous
#include <cuda_runtime.h>
#include <cuda_bf16.h>
#include <math.h>

#define CIN   256
#define HH    64
#define WW    64
#define NPIX  4096
#define BATCH 32
#define KPTS  17

typedef unsigned short ushort_t;
typedef unsigned int   uint_t;

// ---------------------------------------------------------------------------
// Scratch (device globals — no runtime allocation allowed)
// ---------------------------------------------------------------------------
__device__ __align__(1024) ushort_t g_xh[33554432];
__device__ __align__(1024) ushort_t g_xl[33554432];
__device__ __align__(1024) ushort_t g_ah[33554432];
__device__ __align__(1024) ushort_t g_al[33554432];
__device__ __align__(1024) ushort_t g_sh[33554432];
__device__ __align__(1024) ushort_t g_sl[33554432];
__device__ __align__(1024) ushort_t g_th[33554432];
__device__ __align__(1024) ushort_t g_tl[33554432];
__device__ __align__(1024) ushort_t g_wh[2654208];
__device__ __align__(1024) ushort_t g_wl[2654208];

// ---------------------------------------------------------------------------
__device__ __forceinline__ unsigned smem_to_u32(const void* p) {
    unsigned a;
    asm("{ .reg .u64 t; cvta.to.shared.u64 t, %1; cvt.u32.u64 %0, t; }"
        : "=r"(a) : "l"(p));
    return a;
}
__device__ __forceinline__ ushort_t f2h(float v) {
    __nv_bfloat16 b = __float2bfloat16(v);
    return *(ushort_t*)&b;
}
__device__ __forceinline__ float h2f(ushort_t u) {
    __nv_bfloat16 b = *(__nv_bfloat16*)&u;
    return __bfloat162float(b);
}

__device__ __forceinline__ void ldmatrix_x4(uint_t* r, unsigned addr) {
    asm volatile("ldmatrix.sync.aligned.m8n8.x4.shared.b16 {%0,%1,%2,%3}, [%4];"
                 : "=r"(r[0]), "=r"(r[1]), "=r"(r[2]), "=r"(r[3]) : "r"(addr));
}
__device__ __forceinline__ void ldmatrix_x2(uint_t* r, unsigned addr) {
    asm volatile("ldmatrix.sync.aligned.m8n8.x2.shared.b16 {%0,%1}, [%2];"
                 : "=r"(r[0]), "=r"(r[1]) : "r"(addr));
}
__device__ __forceinline__ void mma16816(float* c, const uint_t* a, const uint_t* b) {
    asm volatile(
        "mma.sync.aligned.m16n8k16.row.col.f32.bf16.bf16.f32 "
        "{%0,%1,%2,%3}, {%4,%5,%6,%7}, {%8,%9}, {%0,%1,%2,%3};"
        : "+f"(c[0]), "+f"(c[1]), "+f"(c[2]), "+f"(c[3])
        : "r"(a[0]), "r"(a[1]), "r"(a[2]), "r"(a[3]), "r"(b[0]), "r"(b[1]));
}

// ---------------------------------------------------------------------------
// fp32 -> (bf16 hi, bf16 lo) split of the input tensor
// ---------------------------------------------------------------------------
__global__ __launch_bounds__(256) void split_f32(
    const float* __restrict__ x, ushort_t* __restrict__ h,
    ushort_t* __restrict__ l, int n)
{
    int i = blockIdx.x * 256 + threadIdx.x;
    if (i < n) {
        float v = x[i];
        ushort_t hb = f2h(v);
        h[i] = hb;
        l[i] = f2h(v - h2f(hb));
    }
}

// ---------------------------------------------------------------------------
// Weight prep: reorder w[co][ci][ky][kx] into 36 chunk-tiles (cc = cb*9 + s),
// each [co][64 ci] K-major with SW128 swizzle baked in, hi/lo split.
// Swizzle: off = (co*128 + cii*2) ^ ((co&7)<<4)   (cii*2 < 128 so no self-term)
// ---------------------------------------------------------------------------
__global__ __launch_bounds__(256) void wprep(
    const float* __restrict__ w, ushort_t* __restrict__ wh,
    ushort_t* __restrict__ wl, int CO)
{
    int idx = blockIdx.x * 256 + threadIdx.x;   // < CO*2304 (exact multiple)
    int co = idx / 2304, r = idx % 2304;
    int ci = r / 9, s = r % 9;
    int cb = ci >> 6, cii = ci & 63;
    int cc = cb * 9 + s;
    unsigned off = (unsigned)(co * 128 + cii * 2) ^ (unsigned)((co & 7) << 4);
    size_t dst = (size_t)cc * CO * 64 + (off >> 1);
    float v = w[idx];
    ushort_t hb = f2h(v);
    wh[dst] = hb;
    wl[dst] = f2h(v - h2f(hb));
}

// ---------------------------------------------------------------------------
// 3x3 SAME conv + BN + ReLU via warp-level bf16 mma.sync, hi/lo split (3 passes).
// CTA tile: M=128 pixels (2 rows x 64 cols) x N=128 couts; grid.z = COUT/128.
// 8 warps as 2(M) x 4(N); warp tile 64x32; K in 36 chunks of 64.
// SMEM: A hi/lo 16KB each, B hi/lo 16KB each = 64KB dynamic.
// ---------------------------------------------------------------------------
template <int COUT>
__global__ __launch_bounds__(256, 2) void conv3x3_mma(
    const ushort_t* __restrict__ inh, const ushort_t* __restrict__ inl,
    const ushort_t* __restrict__ wh,  const ushort_t* __restrict__ wl,
    const float* __restrict__ gma, const float* __restrict__ bta,
    ushort_t* __restrict__ outh, ushort_t* __restrict__ outl)
{
    extern __shared__ __align__(1024) char smem[];
    constexpr int A_H = 0, A_L = 16384, B_H = 32768, B_L = 49152;
    const unsigned sb = smem_to_u32(smem);

    const int tid  = threadIdx.x;
    const int wid  = tid >> 5;
    const int lane = tid & 31;
    const int n    = blockIdx.y;
    const int r0   = blockIdx.x * 2;       // first of 2 image rows in this tile
    const int z    = blockIdx.z;

    const int warp_m = wid & 1;            // 0..1  (64 pixels each)
    const int warp_n = wid >> 1;           // 0..3  (32 couts each)

    float acc[4][4][4];
#pragma unroll
    for (int mt = 0; mt < 4; mt++)
#pragma unroll
        for (int nt = 0; nt < 4; nt++)
#pragma unroll
            for (int c = 0; c < 4; c++) acc[mt][nt][c] = 0.f;

    // im2col build coords (per thread: one pixel, 32 ci)
    const int px   = tid & 127;
    const int ci0  = tid >> 7;             // 0/1 -> ci halves
    const int prow = r0 + (px >> 6);
    const int pcol = px & 63;
    const unsigned swz = (unsigned)((px & 7) << 4);

    // ldmatrix lane addressing (byte offsets into tiles)
    const int a_row      = warp_m * 64 + (lane & 15);
    const unsigned a_cb  = (unsigned)((lane >> 4) << 4);        // 0 / 16
    const unsigned a_sw  = (unsigned)((a_row & 7) << 4);
    const int b_row      = warp_n * 32 + (lane & 7);
    const unsigned b_cb  = (unsigned)(((lane >> 3) & 1) << 4);  // 0 / 16
    const unsigned b_sw  = (unsigned)((b_row & 7) << 4);

    int cc = 0;
    for (int cb = 0; cb < 4; cb++) {
        const ushort_t* ph = inh + ((size_t)n * CIN + cb * 64) * NPIX;
        const ushort_t* pl = inl + ((size_t)n * CIN + cb * 64) * NPIX;
        for (int s = 0; s < 9; s++, cc++) {
            const int ky = s / 3, kx = s % 3;
            const int row = prow + ky - 1, col = pcol + kx - 1;
            const bool ok = (row >= 0) && (row < HH) && (col >= 0) && (col < WW);
            const int base = row * WW + col;

            // ---- build im2col A tiles (hi & lo), SW128 layout, 8B stores ----
#pragma unroll
            for (int g = 0; g < 8; g++) {
                const int cib = ci0 * 32 + g * 4;
                uint_t h01 = 0, h23 = 0, l01 = 0, l23 = 0;
                if (ok) {
                    const ushort_t* p0 = ph + (size_t)cib * NPIX + base;
                    const ushort_t* q0 = pl + (size_t)cib * NPIX + base;
                    h01 = (uint_t)p0[0]        | ((uint_t)p0[NPIX]     << 16);
                    h23 = (uint_t)p0[2 * NPIX] | ((uint_t)p0[3 * NPIX] << 16);
                    l01 = (uint_t)q0[0]        | ((uint_t)q0[NPIX]     << 16);
                    l23 = (uint_t)q0[2 * NPIX] | ((uint_t)q0[3 * NPIX] << 16);
                }
                const unsigned off =
                    (unsigned)(px * 128 + ci0 * 64 + g * 8) ^ swz;
                *(uint2*)(smem + A_H + off) = make_uint2(h01, h23);
                *(uint2*)(smem + A_L + off) = make_uint2(l01, l23);
            }
            // ---- copy pre-swizzled weight tiles (128 co x 64 k, hi & lo) ----
            {
                const uint4* s_h = (const uint4*)(wh + (size_t)cc * COUT * 64 + (size_t)z * 8192);
                const uint4* s_l = (const uint4*)(wl + (size_t)cc * COUT * 64 + (size_t)z * 8192);
                uint4* d_h = (uint4*)(smem + B_H);
                uint4* d_l = (uint4*)(smem + B_L);
#pragma unroll
                for (int i = 0; i < 4; i++) {
                    d_h[tid + i * 256] = s_h[tid + i * 256];
                    d_l[tid + i * 256] = s_l[tid + i * 256];
                }
            }
            __syncthreads();

            // ---- compute: 4 k16 steps, 3 split passes ----
#pragma unroll
            for (int k4 = 0; k4 < 4; k4++) {
                const unsigned kb = (unsigned)(k4 * 32);
                uint_t Bh[4][2], Bl[4][2];
#pragma unroll
                for (int nt = 0; nt < 4; nt++) {
                    const unsigned boff =
                        ((unsigned)((b_row + nt * 8) * 128) + kb + b_cb) ^ b_sw;
                    ldmatrix_x2(Bh[nt], sb + B_H + boff);
                    ldmatrix_x2(Bl[nt], sb + B_L + boff);
                }
                uint_t Af[4][4];
#pragma unroll
                for (int mt = 0; mt < 4; mt++) {
                    const unsigned aoff =
                        ((unsigned)((a_row + mt * 16) * 128) + kb + a_cb) ^ a_sw;
                    ldmatrix_x4(Af[mt], sb + A_H + aoff);
                }
#pragma unroll
                for (int mt = 0; mt < 4; mt++)
#pragma unroll
                    for (int nt = 0; nt < 4; nt++) {
                        mma16816(acc[mt][nt], Af[mt], Bh[nt]);   // Ah*Bh
                        mma16816(acc[mt][nt], Af[mt], Bl[nt]);   // Ah*Bl
                    }
#pragma unroll
                for (int mt = 0; mt < 4; mt++) {
                    const unsigned aoff =
                        ((unsigned)((a_row + mt * 16) * 128) + kb + a_cb) ^ a_sw;
                    ldmatrix_x4(Af[mt], sb + A_L + aoff);
                }
#pragma unroll
                for (int mt = 0; mt < 4; mt++)
#pragma unroll
                    for (int nt = 0; nt < 4; nt++)
                        mma16816(acc[mt][nt], Af[mt], Bh[nt]);   // Al*Bh
            }
            __syncthreads();
        }
    }

    // ---- epilogue: BN + ReLU + hi/lo split stores ----
    const float rs = rsqrtf(1.0f + 1e-5f);
    float sc[4][2], bs[4][2];
#pragma unroll
    for (int nt = 0; nt < 4; nt++)
#pragma unroll
        for (int j = 0; j < 2; j++) {
            const int co = z * 128 + warp_n * 32 + nt * 8 + (lane & 3) * 2 + j;
            sc[nt][j] = gma[co] * rs;
            bs[nt][j] = bta[co];
        }

#pragma unroll
    for (int mt = 0; mt < 4; mt++) {
#pragma unroll
        for (int c = 0; c < 4; c++) {
            const int p = warp_m * 64 + mt * 16 + (lane >> 2) + ((c >> 1) << 3);
            const size_t pixoff = (size_t)(r0 + (p >> 6)) * WW + (p & 63);
#pragma unroll
            for (int nt = 0; nt < 4; nt++) {
                const int co = z * 128 + warp_n * 32 + nt * 8 + (lane & 3) * 2 + (c & 1);
                float v = fmaxf(fmaf(acc[mt][nt][c], sc[nt][c & 1], bs[nt][c & 1]), 0.f);
                const size_t o = ((size_t)n * COUT + co) * NPIX + pixoff;
                ushort_t hb = f2h(v);
                outh[o] = hb;
                outl[o] = f2h(v - h2f(hb));
            }
        }
    }
}

// ---------------------------------------------------------------------------
// 1x1 conv head from bf16 hi/lo input; fp32 weights/accumulate; opt. softplus
// ---------------------------------------------------------------------------
template <int CI, int CO, bool SOFTPLUS>
__global__ __launch_bounds__(256) void conv1x1_tc(
    const ushort_t* __restrict__ inh, const ushort_t* __restrict__ inl,
    const float* __restrict__ w, const float* __restrict__ bias,
    float* __restrict__ out)
{
    __shared__ float s_w[CI * CO];   // [ci][co]
    const int tid = threadIdx.x;
    for (int i = tid; i < CI * CO; i += 256)
        s_w[(i % CI) * CO + i / CI] = w[i];
    __syncthreads();

    const int pid = blockIdx.x * 256 + tid;
    const int n = pid >> 12, p = pid & 4095;
    const ushort_t* ph = inh + (size_t)n * CI * NPIX + p;
    const ushort_t* pl = inl + (size_t)n * CI * NPIX + p;

    float acc[CO];
#pragma unroll
    for (int c = 0; c < CO; c++) acc[c] = 0.f;

#pragma unroll 4
    for (int ci = 0; ci < CI; ci++) {
        const float v = h2f(ph[(size_t)ci * NPIX]) + h2f(pl[(size_t)ci * NPIX]);
#pragma unroll
        for (int co = 0; co < CO; co++)
            acc[co] = fmaf(v, s_w[ci * CO + co], acc[co]);
    }
#pragma unroll
    for (int co = 0; co < CO; co++) {
        float v = acc[co] + bias[co];
        if (SOFTPLUS)
            v = (v > 0.f) ? (v + log1pf(expf(-v))) : log1pf(expf(v));
        out[((size_t)n * CO + co) * NPIX + p] = v;
    }
}

// ---------------------------------------------------------------------------
// Fused postprocessing (unchanged from passing R1 kernel)
// ---------------------------------------------------------------------------
__global__ __launch_bounds__(256) void postproc_k(
    const float* __restrict__ heat, const float* __restrict__ off,
    const float* __restrict__ alpha_p, const float* __restrict__ fusion_p,
    float* __restrict__ fw_out, float* __restrict__ coords_out,
    float* __restrict__ scores_out)
{
    __shared__ float r0[256], r1[256], r2[256];
    const int bk  = blockIdx.x;
    const int tid = threadIdx.x;
    const float* hm = heat + (size_t)bk * NPIX;

    float lm = -1e30f;
#pragma unroll
    for (int i = 0; i < 16; i++) lm = fmaxf(lm, hm[tid + i * 256]);
    r0[tid] = lm;
    __syncthreads();
    for (int s = 128; s > 0; s >>= 1) {
        if (tid < s) r0[tid] = fmaxf(r0[tid], r0[tid + s]);
        __syncthreads();
    }
    const float m = r0[0];
    __syncthreads();

    float se = 0.f, sx = 0.f, sy = 0.f;
#pragma unroll
    for (int i = 0; i < 16; i++) {
        const int idx = tid + i * 256;
        const float e = expf(hm[idx] - m);
        se += e;
        sx += e * (float)(idx & 63);
        sy += e * (float)(idx >> 6);
    }
    r0[tid] = se; r1[tid] = sx; r2[tid] = sy;
    __syncthreads();
    for (int s = 128; s > 0; s >>= 1) {
        if (tid < s) {
            r0[tid] += r0[tid + s];
            r1[tid] += r1[tid + s];
            r2[tid] += r2[tid + s];
        }
        __syncthreads();
    }

    if (tid == 0) {
        const float inv = 1.f / r0[0];
        const float xc = r1[0] * inv;
        const float yc = r2[0] * inv;

        const int px = (int)rintf(fminf(fmaxf(xc, 0.f), 63.f));
        const int py = (int)rintf(fminf(fmaxf(yc, 0.f), 63.f));
        int pxs[5], pys[5]; bool okx[5], oky[5];
#pragma unroll
        for (int i = 0; i < 5; i++) {
            const int xs = px - 2 + i; okx[i] = (xs >= 0 && xs < WW); pxs[i] = min(max(xs, 0), 63);
            const int ys = py - 2 + i; oky[i] = (ys >= 0 && ys < HH); pys[i] = min(max(ys, 0), 63);
        }
        float pv[25];
        float pm = -1e30f;
        for (int j = 0; j < 5; j++)
            for (int i = 0; i < 5; i++) {
                const float v = hm[pys[j] * WW + pxs[i]];
                pv[j * 5 + i] = v;
                if (okx[i] && oky[j]) pm = fmaxf(pm, v);
            }
        float ws = 0.f, rx = 0.f, ry = 0.f;
        for (int j = 0; j < 5; j++)
            for (int i = 0; i < 5; i++)
                if (okx[i] && oky[j]) {
                    const float e = expf(pv[j * 5 + i] - pm);
                    ws += e;
                    rx += e * (float)pxs[i];
                    ry += e * (float)pys[j];
                }
        rx /= ws; ry /= ws;

        const float a   = 1.f / (1.f + expf(-alpha_p[0]));
        const float fwv = 1.f / (1.f + expf(-fusion_p[0]));
        float cx = a * xc + (1.f - a) * rx;
        float cy = a * yc + (1.f - a) * ry;

        const float ix = fminf(fmaxf(cx, 0.f), 63.f);
        const float iy = fminf(fmaxf(cy, 0.f), 63.f);
        const float x0f = floorf(ix), y0f = floorf(iy);
        const float wx = ix - x0f, wy = iy - y0f;
        const int x0 = min(max((int)x0f, 0), 63);
        const int y0 = min(max((int)y0f, 0), 63);
        const int x1 = min(x0 + 1, 63);
        const int y1 = min(y0 + 1, 63);
        const float* ob = off + (size_t)bk * 2 * NPIX;
        float sv[2];
#pragma unroll
        for (int ch = 0; ch < 2; ch++) {
            const float* o = ob + ch * NPIX;
            const float v00 = o[y0 * WW + x0], v01 = o[y0 * WW + x1];
            const float v10 = o[y1 * WW + x0], v11 = o[y1 * WW + x1];
            sv[ch] = (1.f - wy) * ((1.f - wx) * v00 + wx * v01)
                   + wy * ((1.f - wx) * v10 + wx * v11);
        }
        cx += fwv * sv[0];
        cy += fwv * sv[1];

        coords_out[bk * 2 + 0] = cx;
        coords_out[bk * 2 + 1] = cy;
        scores_out[bk] = m;
        if (bk == 0) fw_out[0] = fwv;
    }
}

// ---------------------------------------------------------------------------
extern "C" void kernel_launch(void* const* d_in, const int* in_sizes, int n_in,
                              void* d_out, int out_size)
{
    const float* x    = (const float*)d_in[0];
    const float* w_s1 = (const float*)d_in[1];
    const float* g_s1 = (const float*)d_in[2];
    const float* b_s1 = (const float*)d_in[3];
    const float* w_s2 = (const float*)d_in[4];
    const float* g_s2 = (const float*)d_in[5];
    const float* b_s2 = (const float*)d_in[6];
    const float* w_h1 = (const float*)d_in[7];
    const float* g_h1 = (const float*)d_in[8];
    const float* b_h1 = (const float*)d_in[9];
    const float* w_h2 = (const float*)d_in[10];
    const float* c_h2 = (const float*)d_in[11];
    const float* w_o1 = (const float*)d_in[12];
    const float* g_o1 = (const float*)d_in[13];
    const float* b_o1 = (const float*)d_in[14];
    const float* w_o2 = (const float*)d_in[15];
    const float* c_o2 = (const float*)d_in[16];
    const float* w_v1 = (const float*)d_in[17];
    const float* g_v1 = (const float*)d_in[18];
    const float* b_v1 = (const float*)d_in[19];
    const float* w_v2 = (const float*)d_in[20];
    const float* c_v2 = (const float*)d_in[21];
    const float* alpha  = (const float*)d_in[22];
    const float* fusion = (const float*)d_in[23];

    float* out    = (float*)d_out;
    float* heat   = out;
    float* offp   = out + 2228224;
    float* varp   = out + 6684672;
    float* fwp    = out + 8912896;
    float* coords = out + 8912897;
    float* scores = out + 8913985;

    ushort_t *xh, *xl, *ah, *al, *sh, *sl, *th, *tl, *wh, *wl;
    cudaGetSymbolAddress((void**)&xh, g_xh);
    cudaGetSymbolAddress((void**)&xl, g_xl);
    cudaGetSymbolAddress((void**)&ah, g_ah);
    cudaGetSymbolAddress((void**)&al, g_al);
    cudaGetSymbolAddress((void**)&sh, g_sh);
    cudaGetSymbolAddress((void**)&sl, g_sl);
    cudaGetSymbolAddress((void**)&th, g_th);
    cudaGetSymbolAddress((void**)&tl, g_tl);
    cudaGetSymbolAddress((void**)&wh, g_wh);
    cudaGetSymbolAddress((void**)&wl, g_wl);

    const int SMEM = 65536;   // A hi/lo + B hi/lo
    cudaFuncSetAttribute(conv3x3_mma<256>,
        cudaFuncAttributeMaxDynamicSharedMemorySize, SMEM);
    cudaFuncSetAttribute(conv3x3_mma<128>,
        cudaFuncAttributeMaxDynamicSharedMemorySize, SMEM);

    // weight-prep offsets (elements)
    const size_t O_S1 = 0, O_S2 = 589824, O_H1 = 1179648, O_O1 = 1769472, O_V1 = 2359296;

    dim3 blk(256);
    split_f32<<<131072, blk>>>(x, xh, xl, 33554432);
    wprep<<<2304, blk>>>(w_s1, wh + O_S1, wl + O_S1, 256);
    wprep<<<2304, blk>>>(w_s2, wh + O_S2, wl + O_S2, 256);
    wprep<<<2304, blk>>>(w_h1, wh + O_H1, wl + O_H1, 256);
    wprep<<<2304, blk>>>(w_o1, wh + O_O1, wl + O_O1, 256);
    wprep<<<1152, blk>>>(w_v1, wh + O_V1, wl + O_V1, 128);

    dim3 g256(32, BATCH, 2);   // Cout=256
    dim3 g128(32, BATCH, 1);   // Cout=128

    // stem
    conv3x3_mma<256><<<g256, blk, SMEM>>>(xh, xl, wh + O_S1, wl + O_S1, g_s1, b_s1, ah, al);
    conv3x3_mma<256><<<g256, blk, SMEM>>>(ah, al, wh + O_S2, wl + O_S2, g_s2, b_s2, sh, sl);

    // heatmap head
    conv3x3_mma<256><<<g256, blk, SMEM>>>(sh, sl, wh + O_H1, wl + O_H1, g_h1, b_h1, th, tl);
    conv1x1_tc<256, 17, false><<<512, blk>>>(th, tl, w_h2, c_h2, heat);

    // offset head
    conv3x3_mma<256><<<g256, blk, SMEM>>>(sh, sl, wh + O_O1, wl + O_O1, g_o1, b_o1, th, tl);
    conv1x1_tc<256, 34, false><<<512, blk>>>(th, tl, w_o2, c_o2, offp);

    // variance head
    conv3x3_mma<128><<<g128, blk, SMEM>>>(sh, sl, wh + O_V1, wl + O_V1, g_v1, b_v1, th, tl);
    conv1x1_tc<128, 17, true><<<512, blk>>>(th, tl, w_v2, c_v2, varp);

    // fused soft-argmax + refine + offset sampling
    postproc_k<<<BATCH * KPTS, blk>>>(heat, offp, alpha, fusion, fwp, coords, scores);
}